// round 9
// baseline (speedup 1.0000x reference)
#include <cuda_runtime.h>
#include <cuda_bf16.h>
#include <cstdint>

// RWKV TimeMix on GB300 (compute_103-safe tensor path):
//   mix(bf16 split) -> 3x HMMA GEMM (k,v,r) -> WKV*sigmoid(r) (bf16 split y)
//   -> HMMA output GEMM.
// GEMM: D[m,d] = sum_c A[m,c]*W[d,c]; fp32 accuracy via bf16 3-term split:
//   D = Ah*Wh + Ah*Wl + Al*Wh     (lo*lo dropped, ~2^-18 relative)

#define BB 32
#define TT 256
#define CC 1024
#define MROWS (BB * TT)                 // 8192
#define SZ (BB * TT * CC)               // 8,388,608
#define WSZ (CC * CC)                   // 1,048,576

// ------------------------- device scratch (no allocs) -----------------------
__device__ __nv_bfloat16 g_a_hi[3 * SZ];
__device__ __nv_bfloat16 g_a_lo[3 * SZ];
__device__ __nv_bfloat16 g_w_hi[4 * WSZ];
__device__ __nv_bfloat16 g_w_lo[4 * WSZ];
__device__ float         g_kvr[3 * SZ];
__device__ __nv_bfloat16 g_y_hi[SZ];
__device__ __nv_bfloat16 g_y_lo[SZ];

// ------------------------------ PTX helpers --------------------------------
__device__ __forceinline__ uint32_t smem_u32(const void* p) {
    uint32_t a;
    asm("{ .reg .u64 t; cvta.to.shared.u64 t, %1; cvt.u32.u64 %0, t; }"
        : "=r"(a) : "l"(p));
    return a;
}
__device__ __forceinline__ void cp16(uint32_t dst, const void* src) {
    asm volatile("cp.async.cg.shared.global [%0], [%1], 16;" :: "r"(dst), "l"(src));
}
#define CP_COMMIT() asm volatile("cp.async.commit_group;" ::: "memory")
#define CP_WAIT(n)  asm volatile("cp.async.wait_group %0;" :: "n"(n) : "memory")

__device__ __forceinline__ void ldsm4(uint32_t* r, uint32_t a) {
    asm volatile("ldmatrix.sync.aligned.m8n8.x4.shared.b16 {%0,%1,%2,%3}, [%4];"
        : "=r"(r[0]), "=r"(r[1]), "=r"(r[2]), "=r"(r[3]) : "r"(a));
}
__device__ __forceinline__ void mma16816(float* c, const uint32_t* a, const uint32_t* b) {
    asm volatile("mma.sync.aligned.m16n8k16.row.col.f32.bf16.bf16.f32 "
        "{%0,%1,%2,%3}, {%4,%5,%6,%7}, {%8,%9}, {%0,%1,%2,%3};"
        : "+f"(c[0]), "+f"(c[1]), "+f"(c[2]), "+f"(c[3])
        : "r"(a[0]), "r"(a[1]), "r"(a[2]), "r"(a[3]), "r"(b[0]), "r"(b[1]));
}

__device__ __forceinline__ void split2(float a, float b, uint32_t& h2, uint32_t& l2) {
    asm("cvt.rn.bf16x2.f32 %0, %1, %2;" : "=r"(h2) : "f"(b), "f"(a));
    float ha = __uint_as_float(h2 << 16);
    float hb = __uint_as_float(h2 & 0xFFFF0000u);
    asm("cvt.rn.bf16x2.f32 %0, %1, %2;" : "=r"(l2) : "f"(b - hb), "f"(a - ha));
}

// ------------------------------ GEMM config --------------------------------
// 512 threads, 16 warps, CTA 256x128, warp tile 64x32 (no register spills).
#define CTA_M 256
#define CTA_N 128
#define NTHREADS 512
#define KCHUNK 32
#define NCHUNK (CC / KCHUNK)       // 32
#define LDS_ROW 40                 // bf16/row: 32 data + 8 pad
#define ROWB (LDS_ROW * 2)         // 80 B; conflict-free ldmatrix stride
#define SM_AH 0
#define SM_AL 20480                // 256*80
#define SM_WH 40960
#define SM_WL 51200                // +128*80
#define STAGE 61440
#define SMEM_BYTES (2 * STAGE)     // 122880

__device__ __forceinline__ void gemm_mma_body(
    const __nv_bfloat16* __restrict__ Ahi, const __nv_bfloat16* __restrict__ Alo,
    const __nv_bfloat16* __restrict__ Whi, const __nv_bfloat16* __restrict__ Wlo,
    float* __restrict__ D)
{
    extern __shared__ char smem[];
    const uint32_t sb = smem_u32(smem);
    const int tid = threadIdx.x;
    const int wid = tid >> 5;
    const int lane = tid & 31;
    const int wm = wid >> 2;              // 0..3  (64-row band)
    const int wn = wid & 3;               // 0..3  (32-col band)
    const int gm = blockIdx.y * CTA_M;
    const int gn = blockIdx.x * CTA_N;

    float acc[4][4][4];
#pragma unroll
    for (int i = 0; i < 4; i++)
#pragma unroll
        for (int j = 0; j < 4; j++)
#pragma unroll
            for (int q = 0; q < 4; q++) acc[i][j][q] = 0.f;

    // lane-invariant ldmatrix offsets
    const int a_row = wm * 64 + (lane & 7) + ((lane >> 3) & 1) * 8;  // + mi*16
    const int a_kof = (lane >> 4) * 8;                               // + k0
    const int b_row = wn * 32 + lane;

    const __nv_bfloat16* gA[2] = { Ahi + (size_t)gm * CC, Alo + (size_t)gm * CC };
    const __nv_bfloat16* gW[2] = { Whi + (size_t)gn * CC, Wlo + (size_t)gn * CC };

    // 3072 x 16B per chunk, 6 per thread
#define LOAD_CHUNK(ck, stg) do {                                              \
    uint32_t s0 = sb + (stg) * STAGE;                                         \
    int kc = (ck) * KCHUNK;                                                   \
    _Pragma("unroll")                                                         \
    for (int i = 0; i < 6; i++) {                                             \
        int idx = tid + i * NTHREADS;                                         \
        if (i < 4) {                                                          \
            int ty = idx >> 10, rem = idx & 1023;                             \
            int row = rem >> 2, c = rem & 3;                                  \
            cp16(s0 + ty * 20480 + row * ROWB + c * 16,                       \
                 gA[ty] + (size_t)row * CC + kc + c * 8);                     \
        } else {                                                              \
            int w = idx - 2048;                                               \
            int ty = w >> 9, rem = w & 511;                                   \
            int row = rem >> 2, c = rem & 3;                                  \
            cp16(s0 + 40960 + ty * 10240 + row * ROWB + c * 16,               \
                 gW[ty] + (size_t)row * CC + kc + c * 8);                     \
        }                                                                     \
    }                                                                         \
    CP_COMMIT();                                                              \
} while (0)

    LOAD_CHUNK(0, 0);

    for (int ck = 0; ck < NCHUNK; ck++) {
        const int stg = ck & 1;
        if (ck + 1 < NCHUNK) { LOAD_CHUNK(ck + 1, stg ^ 1); CP_WAIT(1); }
        else                 { CP_WAIT(0); }
        __syncthreads();

        const uint32_t s0 = sb + stg * STAGE;
#pragma unroll
        for (int k0 = 0; k0 < KCHUNK; k0 += 16) {
            // W fragments for this warp's 32-col band (hi + lo, both k-halves)
            uint32_t t0[4], t1[4], u0[4], u1[4];
            {
                uint32_t base = s0 + SM_WH + (uint32_t)(b_row * ROWB + k0 * 2);
                ldsm4(t0, base);
                ldsm4(t1, base + 16);
                ldsm4(u0, base + (SM_WL - SM_WH));
                ldsm4(u1, base + (SM_WL - SM_WH) + 16);
            }
#pragma unroll
            for (int mi = 0; mi < 4; mi++) {
                uint32_t ah[4], al[4];
                uint32_t addr = s0 + SM_AH +
                    (uint32_t)((a_row + mi * 16) * ROWB + (k0 + a_kof) * 2);
                ldsm4(ah, addr);
                ldsm4(al, addr + (SM_AL - SM_AH));
#pragma unroll
                for (int s = 0; s < 4; s++) {
                    uint32_t bh[2] = { t0[s], t1[s] };
                    uint32_t bl[2] = { u0[s], u1[s] };
                    float* a = acc[mi][s];
                    mma16816(a, ah, bh);
                    mma16816(a, ah, bl);
                    mma16816(a, al, bh);
                }
            }
        }
        __syncthreads();
    }
#undef LOAD_CHUNK

    const int trow = lane >> 2;
    const int tcol = (lane & 3) * 2;
#pragma unroll
    for (int mi = 0; mi < 4; mi++) {
#pragma unroll
        for (int ni = 0; ni < 4; ni++) {
            float* dp = D + (size_t)(gm + wm * 64 + mi * 16 + trow) * CC
                          + gn + wn * 32 + ni * 8 + tcol;
            float2 v0 = { acc[mi][ni][0], acc[mi][ni][1] };
            float2 v1 = { acc[mi][ni][2], acc[mi][ni][3] };
            *(float2*)dp = v0;
            *(float2*)(dp + 8 * CC) = v1;
        }
    }
}

__global__ __launch_bounds__(NTHREADS, 1)
void gemm3_mma() {
    const int z = blockIdx.z;
    gemm_mma_body(g_a_hi + (size_t)z * SZ, g_a_lo + (size_t)z * SZ,
                  g_w_hi + (size_t)z * WSZ, g_w_lo + (size_t)z * WSZ,
                  g_kvr + (size_t)z * SZ);
}

__global__ __launch_bounds__(NTHREADS, 1)
void gemm_out_mma(float* __restrict__ out) {
    gemm_mma_body(g_y_hi, g_y_lo, g_w_hi + 3 * WSZ, g_w_lo + 3 * WSZ, out);
}

// ------------------------------- mix kernel ---------------------------------
__global__ void mix_kernel(const float* __restrict__ x,
                           const float* __restrict__ tmk,
                           const float* __restrict__ tmv,
                           const float* __restrict__ tmr) {
    const int n4 = SZ / 4;
    int i = blockIdx.x * blockDim.x + threadIdx.x;
    if (i >= n4) return;
    const int cpt = CC / 4;
    int c4 = i & (cpt - 1);
    int t  = (i / cpt) & (TT - 1);

    const float4* x4 = (const float4*)x;
    float4 xc = x4[i];
    float4 xp = make_float4(0.f, 0.f, 0.f, 0.f);
    if (t != 0) xp = x4[i - cpt];

    const float4 ms[3] = { ((const float4*)tmk)[c4],
                           ((const float4*)tmv)[c4],
                           ((const float4*)tmr)[c4] };
#pragma unroll
    for (int z = 0; z < 3; z++) {
        float4 m = ms[z];
        float a = xp.x + m.x * (xc.x - xp.x);
        float b = xp.y + m.y * (xc.y - xp.y);
        float c = xp.z + m.z * (xc.z - xp.z);
        float d = xp.w + m.w * (xc.w - xp.w);
        uint2 h, l;
        split2(a, b, h.x, l.x);
        split2(c, d, h.y, l.y);
        ((uint2*)g_a_hi)[(size_t)z * (SZ / 4) + i] = h;
        ((uint2*)g_a_lo)[(size_t)z * (SZ / 4) + i] = l;
    }
}

// --------------------------- weight split kernel ----------------------------
__global__ void wsplit_kernel(const float* __restrict__ Wk, const float* __restrict__ Wv,
                              const float* __restrict__ Wr, const float* __restrict__ Wo) {
    int i = blockIdx.x * blockDim.x + threadIdx.x;
    const int per = WSZ / 4;
    if (i >= 4 * per) return;
    int z = i >> 18;
    int loc = i & (per - 1);
    const float* W = (z == 0) ? Wk : (z == 1) ? Wv : (z == 2) ? Wr : Wo;
    float4 v = ((const float4*)W)[loc];
    uint2 h, l;
    split2(v.x, v.y, h.x, l.x);
    split2(v.z, v.w, h.y, l.y);
    ((uint2*)g_w_hi)[(size_t)z * per + loc] = h;
    ((uint2*)g_w_lo)[(size_t)z * per + loc] = l;
}

// ------------------------------- WKV kernel ---------------------------------
// Latency-bound serial scan -> software-pipelined register double buffer of
// PF timesteps (3*PF independent loads in flight while the serial exp chain
// of the previous block executes).
#define PF 8
__global__ void wkv_kernel(const float* __restrict__ time_decay,
                           const float* __restrict__ time_first) {
    int gid = blockIdx.x * blockDim.x + threadIdx.x;
    if (gid >= BB * CC) return;
    int b = gid / CC;
    int c = gid & (CC - 1);

    const float* kk = g_kvr;
    const float* vv = g_kvr + SZ;
    const float* rr = g_kvr + 2 * (size_t)SZ;

    float w = -__expf(time_decay[c]);
    float u = time_first[c];

    float p = 0.f, q = 0.f, o = -1e38f;
    const size_t base = (size_t)b * TT * CC + c;

    float kb[2][PF], vb[2][PF], rb[2][PF];
#pragma unroll
    for (int j = 0; j < PF; j++) {
        size_t off = base + (size_t)j * CC;
        kb[0][j] = kk[off]; vb[0][j] = vv[off]; rb[0][j] = rr[off];
    }

    for (int t0 = 0; t0 < TT; t0 += PF) {
        const int cur = (t0 / PF) & 1;
        const int nxt = cur ^ 1;
        if (t0 + PF < TT) {
#pragma unroll
            for (int j = 0; j < PF; j++) {
                size_t off = base + (size_t)(t0 + PF + j) * CC;
                kb[nxt][j] = kk[off]; vb[nxt][j] = vv[off]; rb[nxt][j] = rr[off];
            }
        }
#pragma unroll
        for (int j = 0; j < PF; j++) {
            float kt = kb[cur][j];
            float vt = vb[cur][j];
            float rt = rb[cur][j];

            float uk = u + kt;
            float no = fmaxf(o, uk);
            float eA = __expf(o - no);
            float eB = __expf(uk - no);
            float y  = __fdividef(eA * p + eB * vt, eA * q + eB);

            float sr = __fdividef(1.f, 1.f + __expf(-rt));
            float f = sr * y;
            __nv_bfloat16 h = __float2bfloat16(f);
            size_t off = base + (size_t)(t0 + j) * CC;
            g_y_hi[off] = h;
            g_y_lo[off] = __float2bfloat16(f - __bfloat162float(h));

            float wo  = w + o;
            float no2 = fmaxf(wo, kt);
            float A2  = __expf(wo - no2);
            float B2  = __expf(kt - no2);
            p = A2 * p + B2 * vt;
            q = A2 * q + B2;
            o = no2;
        }
    }
}

// ---------------------------------------------------------------------------
extern "C" void kernel_launch(void* const* d_in, const int* in_sizes, int n_in,
                              void* d_out, int out_size) {
    const float* x   = (const float*)d_in[0];
    const float* td  = (const float*)d_in[1];
    const float* tf  = (const float*)d_in[2];
    const float* tmk = (const float*)d_in[3];
    const float* tmv = (const float*)d_in[4];
    const float* tmr = (const float*)d_in[5];
    const float* Wk  = (const float*)d_in[6];
    const float* Wv  = (const float*)d_in[7];
    const float* Wr  = (const float*)d_in[8];
    const float* Wo  = (const float*)d_in[9];
    float* out = (float*)d_out;

    static bool attr_set = false;
    if (!attr_set) {
        cudaFuncSetAttribute(gemm3_mma, cudaFuncAttributeMaxDynamicSharedMemorySize, SMEM_BYTES);
        cudaFuncSetAttribute(gemm_out_mma, cudaFuncAttributeMaxDynamicSharedMemorySize, SMEM_BYTES);
        attr_set = true;
    }

    const int n4 = SZ / 4;
    mix_kernel<<<(n4 + 255) / 256, 256>>>(x, tmk, tmv, tmr);
    wsplit_kernel<<<(WSZ + 255) / 256, 256>>>(Wk, Wv, Wr, Wo);

    dim3 g3(CC / CTA_N, MROWS / CTA_M, 3);
    gemm3_mma<<<g3, NTHREADS, SMEM_BYTES>>>();

    wkv_kernel<<<(BB * CC + 127) / 128, 128>>>(td, tf);

    dim3 go(CC / CTA_N, MROWS / CTA_M, 1);
    gemm_out_mma<<<go, NTHREADS, SMEM_BYTES>>>(out);
}

// round 10
// speedup vs baseline: 1.4602x; 1.4602x over previous
#include <cuda_runtime.h>
#include <cuda_bf16.h>
#include <cstdint>

// RWKV TimeMix on GB300 (compute_103-safe tensor path):
//   mix(bf16 split) -> 3x HMMA GEMM (k,v,r) -> WKV*sigmoid(r) (bf16 split y)
//   -> HMMA output GEMM.
// GEMM: D[m,d] = sum_c A[m,c]*W[d,c]; fp32 accuracy via bf16 3-term split:
//   D = Ah*Wh + Ah*Wl + Al*Wh     (lo*lo dropped, ~2^-18 relative)
// GEMM tiling: R8 config (256 thr, 8 warps, warp tile 64x64) — measured
// near the legacy-HMMA pipe floor; do not shrink warp tiles (R9 regression).

#define BB 32
#define TT 256
#define CC 1024
#define MROWS (BB * TT)                 // 8192
#define SZ (BB * TT * CC)               // 8,388,608
#define WSZ (CC * CC)                   // 1,048,576

// ------------------------- device scratch (no allocs) -----------------------
__device__ __nv_bfloat16 g_a_hi[3 * SZ];
__device__ __nv_bfloat16 g_a_lo[3 * SZ];
__device__ __nv_bfloat16 g_w_hi[4 * WSZ];
__device__ __nv_bfloat16 g_w_lo[4 * WSZ];
__device__ float         g_kvr[3 * SZ];
__device__ __nv_bfloat16 g_y_hi[SZ];
__device__ __nv_bfloat16 g_y_lo[SZ];

// ------------------------------ PTX helpers --------------------------------
__device__ __forceinline__ uint32_t smem_u32(const void* p) {
    uint32_t a;
    asm("{ .reg .u64 t; cvta.to.shared.u64 t, %1; cvt.u32.u64 %0, t; }"
        : "=r"(a) : "l"(p));
    return a;
}
__device__ __forceinline__ void cp16(uint32_t dst, const void* src) {
    asm volatile("cp.async.cg.shared.global [%0], [%1], 16;" :: "r"(dst), "l"(src));
}
#define CP_COMMIT() asm volatile("cp.async.commit_group;" ::: "memory")
#define CP_WAIT(n)  asm volatile("cp.async.wait_group %0;" :: "n"(n) : "memory")

__device__ __forceinline__ void ldsm4(uint32_t* r, uint32_t a) {
    asm volatile("ldmatrix.sync.aligned.m8n8.x4.shared.b16 {%0,%1,%2,%3}, [%4];"
        : "=r"(r[0]), "=r"(r[1]), "=r"(r[2]), "=r"(r[3]) : "r"(a));
}
__device__ __forceinline__ void mma16816(float* c, const uint32_t* a, const uint32_t* b) {
    asm volatile("mma.sync.aligned.m16n8k16.row.col.f32.bf16.bf16.f32 "
        "{%0,%1,%2,%3}, {%4,%5,%6,%7}, {%8,%9}, {%0,%1,%2,%3};"
        : "+f"(c[0]), "+f"(c[1]), "+f"(c[2]), "+f"(c[3])
        : "r"(a[0]), "r"(a[1]), "r"(a[2]), "r"(a[3]), "r"(b[0]), "r"(b[1]));
}

__device__ __forceinline__ void split2(float a, float b, uint32_t& h2, uint32_t& l2) {
    asm("cvt.rn.bf16x2.f32 %0, %1, %2;" : "=r"(h2) : "f"(b), "f"(a));
    float ha = __uint_as_float(h2 << 16);
    float hb = __uint_as_float(h2 & 0xFFFF0000u);
    asm("cvt.rn.bf16x2.f32 %0, %1, %2;" : "=r"(l2) : "f"(b - hb), "f"(a - ha));
}

// ------------------------------ GEMM config (R8) ---------------------------
#define CTA_M 256
#define CTA_N 128
#define KCHUNK 32
#define NCHUNK (CC / KCHUNK)       // 32
#define LDS_ROW 40                  // bf16/row: 32 data + 8 pad
#define ROWB (LDS_ROW * 2)          // 80 bytes; conflict-free ldmatrix stride
#define SM_AH 0
#define SM_AL 20480                 // 256*80
#define SM_WH 40960
#define SM_WL 51200                 // +128*80
#define STAGE 61440
#define SMEM_BYTES (2 * STAGE)      // 122880

__device__ __forceinline__ void gemm_mma_body(
    const __nv_bfloat16* __restrict__ Ahi, const __nv_bfloat16* __restrict__ Alo,
    const __nv_bfloat16* __restrict__ Whi, const __nv_bfloat16* __restrict__ Wlo,
    float* __restrict__ D)
{
    extern __shared__ char smem[];
    const uint32_t sb = smem_u32(smem);
    const int tid = threadIdx.x;
    const int wid = tid >> 5;
    const int lane = tid & 31;
    const int wm = wid >> 1;              // 0..3  (64-row band)
    const int wn = wid & 1;               // 0..1  (64-col band)
    const int gm = blockIdx.y * CTA_M;
    const int gn = blockIdx.x * CTA_N;

    float acc[4][8][4];
#pragma unroll
    for (int i = 0; i < 4; i++)
#pragma unroll
        for (int j = 0; j < 8; j++)
#pragma unroll
            for (int q = 0; q < 4; q++) acc[i][j][q] = 0.f;

    const int a_row = wm * 64 + (lane & 7) + ((lane >> 3) & 1) * 8;  // + mi*16
    const int a_kof = (lane >> 4) * 8;                               // + k0
    const int b_row = wn * 64 + lane;                                // + g*32

    const __nv_bfloat16* gA[2] = { Ahi + (size_t)gm * CC, Alo + (size_t)gm * CC };
    const __nv_bfloat16* gW[2] = { Whi + (size_t)gn * CC, Wlo + (size_t)gn * CC };

#define LOAD_CHUNK(ck, stg) do {                                              \
    uint32_t s0 = sb + (stg) * STAGE;                                         \
    int kc = (ck) * KCHUNK;                                                   \
    _Pragma("unroll")                                                         \
    for (int i = 0; i < 12; i++) {                                            \
        int idx = tid + i * 256;                                              \
        if (i < 8) {                                                          \
            int ty = idx >> 10, rem = idx & 1023;                             \
            int row = rem >> 2, c = rem & 3;                                  \
            cp16(s0 + ty * 20480 + row * ROWB + c * 16,                       \
                 gA[ty] + (size_t)row * CC + kc + c * 8);                     \
        } else {                                                              \
            int w = idx - 2048;                                               \
            int ty = w >> 9, rem = w & 511;                                   \
            int row = rem >> 2, c = rem & 3;                                  \
            cp16(s0 + 40960 + ty * 10240 + row * ROWB + c * 16,               \
                 gW[ty] + (size_t)row * CC + kc + c * 8);                     \
        }                                                                     \
    }                                                                         \
    CP_COMMIT();                                                              \
} while (0)

    LOAD_CHUNK(0, 0);

    for (int ck = 0; ck < NCHUNK; ck++) {
        const int stg = ck & 1;
        if (ck + 1 < NCHUNK) { LOAD_CHUNK(ck + 1, stg ^ 1); CP_WAIT(1); }
        else                 { CP_WAIT(0); }
        __syncthreads();

        const uint32_t s0 = sb + stg * STAGE;
#pragma unroll
        for (int k0 = 0; k0 < KCHUNK; k0 += 16) {
            uint32_t ah[4][4], al[4][4];
#pragma unroll
            for (int mi = 0; mi < 4; mi++) {
                uint32_t addr = s0 + SM_AH + (uint32_t)((a_row + mi * 16) * ROWB + (k0 + a_kof) * 2);
                ldsm4(ah[mi], addr);
                ldsm4(al[mi], addr + (SM_AL - SM_AH));
            }
#pragma unroll
            for (int g = 0; g < 2; g++) {
                uint32_t t0[4], t1[4], u0[4], u1[4];
                uint32_t base = s0 + SM_WH + (uint32_t)((b_row + g * 32) * ROWB + k0 * 2);
                ldsm4(t0, base);
                ldsm4(t1, base + 16);
                ldsm4(u0, base + (SM_WL - SM_WH));
                ldsm4(u1, base + (SM_WL - SM_WH) + 16);
#pragma unroll
                for (int s = 0; s < 4; s++) {
                    uint32_t bh[2] = { t0[s], t1[s] };
                    uint32_t bl[2] = { u0[s], u1[s] };
#pragma unroll
                    for (int mi = 0; mi < 4; mi++) {
                        float* a = acc[mi][g * 4 + s];
                        mma16816(a, ah[mi], bh);
                        mma16816(a, ah[mi], bl);
                        mma16816(a, al[mi], bh);
                    }
                }
            }
        }
        __syncthreads();
    }
#undef LOAD_CHUNK

    const int trow = lane >> 2;
    const int tcol = (lane & 3) * 2;
#pragma unroll
    for (int mi = 0; mi < 4; mi++) {
#pragma unroll
        for (int ni = 0; ni < 8; ni++) {
            float* dp = D + (size_t)(gm + wm * 64 + mi * 16 + trow) * CC
                          + gn + wn * 64 + ni * 8 + tcol;
            float2 v0 = { acc[mi][ni][0], acc[mi][ni][1] };
            float2 v1 = { acc[mi][ni][2], acc[mi][ni][3] };
            *(float2*)dp = v0;
            *(float2*)(dp + 8 * CC) = v1;
        }
    }
}

__global__ __launch_bounds__(256, 1)
void gemm3_mma() {
    const int z = blockIdx.z;
    gemm_mma_body(g_a_hi + (size_t)z * SZ, g_a_lo + (size_t)z * SZ,
                  g_w_hi + (size_t)z * WSZ, g_w_lo + (size_t)z * WSZ,
                  g_kvr + (size_t)z * SZ);
}

__global__ __launch_bounds__(256, 1)
void gemm_out_mma(float* __restrict__ out) {
    gemm_mma_body(g_y_hi, g_y_lo, g_w_hi + 3 * WSZ, g_w_lo + 3 * WSZ, out);
}

// ------------------------------- mix kernel ---------------------------------
__global__ void mix_kernel(const float* __restrict__ x,
                           const float* __restrict__ tmk,
                           const float* __restrict__ tmv,
                           const float* __restrict__ tmr) {
    const int n4 = SZ / 4;
    int i = blockIdx.x * blockDim.x + threadIdx.x;
    if (i >= n4) return;
    const int cpt = CC / 4;
    int c4 = i & (cpt - 1);
    int t  = (i / cpt) & (TT - 1);

    const float4* x4 = (const float4*)x;
    float4 xc = x4[i];
    float4 xp = make_float4(0.f, 0.f, 0.f, 0.f);
    if (t != 0) xp = x4[i - cpt];

    const float4 ms[3] = { ((const float4*)tmk)[c4],
                           ((const float4*)tmv)[c4],
                           ((const float4*)tmr)[c4] };
#pragma unroll
    for (int z = 0; z < 3; z++) {
        float4 m = ms[z];
        float a = xp.x + m.x * (xc.x - xp.x);
        float b = xp.y + m.y * (xc.y - xp.y);
        float c = xp.z + m.z * (xc.z - xp.z);
        float d = xp.w + m.w * (xc.w - xp.w);
        uint2 h, l;
        split2(a, b, h.x, l.x);
        split2(c, d, h.y, l.y);
        ((uint2*)g_a_hi)[(size_t)z * (SZ / 4) + i] = h;
        ((uint2*)g_a_lo)[(size_t)z * (SZ / 4) + i] = l;
    }
}

// --------------------------- weight split kernel ----------------------------
__global__ void wsplit_kernel(const float* __restrict__ Wk, const float* __restrict__ Wv,
                              const float* __restrict__ Wr, const float* __restrict__ Wo) {
    int i = blockIdx.x * blockDim.x + threadIdx.x;
    const int per = WSZ / 4;
    if (i >= 4 * per) return;
    int z = i >> 18;
    int loc = i & (per - 1);
    const float* W = (z == 0) ? Wk : (z == 1) ? Wv : (z == 2) ? Wr : Wo;
    float4 v = ((const float4*)W)[loc];
    uint2 h, l;
    split2(v.x, v.y, h.x, l.x);
    split2(v.z, v.w, h.y, l.y);
    ((uint2*)g_w_hi)[(size_t)z * per + loc] = h;
    ((uint2*)g_w_lo)[(size_t)z * per + loc] = l;
}

// ------------------------------- WKV kernel ---------------------------------
// 2 independent scan chains per thread (channels c and c+512) + PF-step
// register double buffer: doubles issue ILP and load MLP per warp.
#define PF 4
__global__ void wkv_kernel(const float* __restrict__ time_decay,
                           const float* __restrict__ time_first) {
    int gid = blockIdx.x * blockDim.x + threadIdx.x;      // 0..16383
    if (gid >= BB * CC / 2) return;
    int b  = gid >> 9;            // /512
    int cb = gid & 511;

    const float* kk = g_kvr;
    const float* vv = g_kvr + SZ;
    const float* rr = g_kvr + 2 * (size_t)SZ;

    float w[2], u[2], p[2], q[2], o[2];
    size_t base[2];
#pragma unroll
    for (int h = 0; h < 2; h++) {
        int c = cb + h * 512;
        w[h] = -__expf(time_decay[c]);
        u[h] = time_first[c];
        p[h] = 0.f; q[h] = 0.f; o[h] = -1e38f;
        base[h] = (size_t)b * TT * CC + c;
    }

    float kb[2][2][PF], vb[2][2][PF], rb[2][2][PF];
#pragma unroll
    for (int h = 0; h < 2; h++)
#pragma unroll
        for (int j = 0; j < PF; j++) {
            size_t off = base[h] + (size_t)j * CC;
            kb[h][0][j] = kk[off]; vb[h][0][j] = vv[off]; rb[h][0][j] = rr[off];
        }

    for (int t0 = 0; t0 < TT; t0 += PF) {
        const int cur = (t0 / PF) & 1;
        const int nxt = cur ^ 1;
        if (t0 + PF < TT) {
#pragma unroll
            for (int h = 0; h < 2; h++)
#pragma unroll
                for (int j = 0; j < PF; j++) {
                    size_t off = base[h] + (size_t)(t0 + PF + j) * CC;
                    kb[h][nxt][j] = kk[off];
                    vb[h][nxt][j] = vv[off];
                    rb[h][nxt][j] = rr[off];
                }
        }
#pragma unroll
        for (int j = 0; j < PF; j++) {
#pragma unroll
            for (int h = 0; h < 2; h++) {
                float kt = kb[h][cur][j];
                float vt = vb[h][cur][j];
                float rt = rb[h][cur][j];

                float uk = u[h] + kt;
                float no = fmaxf(o[h], uk);
                float eA = __expf(o[h] - no);
                float eB = __expf(uk - no);
                float y  = __fdividef(eA * p[h] + eB * vt, eA * q[h] + eB);

                float sr = __fdividef(1.f, 1.f + __expf(-rt));
                float f = sr * y;
                __nv_bfloat16 hh = __float2bfloat16(f);
                size_t off = base[h] + (size_t)(t0 + j) * CC;
                g_y_hi[off] = hh;
                g_y_lo[off] = __float2bfloat16(f - __bfloat162float(hh));

                float wo  = w[h] + o[h];
                float no2 = fmaxf(wo, kt);
                float A2  = __expf(wo - no2);
                float B2  = __expf(kt - no2);
                p[h] = A2 * p[h] + B2 * vt;
                q[h] = A2 * q[h] + B2;
                o[h] = no2;
            }
        }
    }
}

// ---------------------------------------------------------------------------
extern "C" void kernel_launch(void* const* d_in, const int* in_sizes, int n_in,
                              void* d_out, int out_size) {
    const float* x   = (const float*)d_in[0];
    const float* td  = (const float*)d_in[1];
    const float* tf  = (const float*)d_in[2];
    const float* tmk = (const float*)d_in[3];
    const float* tmv = (const float*)d_in[4];
    const float* tmr = (const float*)d_in[5];
    const float* Wk  = (const float*)d_in[6];
    const float* Wv  = (const float*)d_in[7];
    const float* Wr  = (const float*)d_in[8];
    const float* Wo  = (const float*)d_in[9];
    float* out = (float*)d_out;

    static bool attr_set = false;
    if (!attr_set) {
        cudaFuncSetAttribute(gemm3_mma, cudaFuncAttributeMaxDynamicSharedMemorySize, SMEM_BYTES);
        cudaFuncSetAttribute(gemm_out_mma, cudaFuncAttributeMaxDynamicSharedMemorySize, SMEM_BYTES);
        attr_set = true;
    }

    const int n4 = SZ / 4;
    mix_kernel<<<(n4 + 255) / 256, 256>>>(x, tmk, tmv, tmr);
    wsplit_kernel<<<(WSZ + 255) / 256, 256>>>(Wk, Wv, Wr, Wo);

    dim3 g3(CC / CTA_N, MROWS / CTA_M, 3);
    gemm3_mma<<<g3, 256, SMEM_BYTES>>>();

    wkv_kernel<<<(BB * CC / 2 + 127) / 128, 128>>>(td, tf);

    dim3 go(CC / CTA_N, MROWS / CTA_M, 1);
    gemm_out_mma<<<go, 256, SMEM_BYTES>>>(out);
}

// round 12
// speedup vs baseline: 1.5964x; 1.0933x over previous
#include <cuda_runtime.h>
#include <cuda_bf16.h>
#include <cstdint>

// RWKV TimeMix on GB300 (compute_103-safe tensor path):
//   mix(bf16 split) -> 3x HMMA GEMM (k,v,r) -> WKV (3-phase parallel scan,
//   sigmoid gate, bf16-split y) -> HMMA output GEMM.
// GEMM: D[m,d] = sum_c A[m,c]*W[d,c]; fp32 accuracy via bf16 3-term split:
//   D = Ah*Wh + Ah*Wl + Al*Wh     (lo*lo dropped, ~2^-18 relative)
// GEMM tiling: R8 config (256 thr, 8 warps, warp tile 64x64) — measured
// co-bound on smem BW + HMMA pipe; do not retile (R9 regression).

#define BB 32
#define TT 256
#define CC 1024
#define MROWS (BB * TT)                 // 8192
#define SZ (BB * TT * CC)               // 8,388,608
#define WSZ (CC * CC)                   // 1,048,576
#define SEG 8
#define SEGLEN (TT / SEG)               // 32
#define NSEGST (BB * SEG * CC)          // 262144

// ------------------------- device scratch (no allocs) -----------------------
__device__ __nv_bfloat16 g_a_hi[3 * SZ];
__device__ __nv_bfloat16 g_a_lo[3 * SZ];
__device__ __nv_bfloat16 g_w_hi[4 * WSZ];
__device__ __nv_bfloat16 g_w_lo[4 * WSZ];
__device__ float         g_kvr[3 * SZ];
__device__ __nv_bfloat16 g_y_hi[SZ];
__device__ __nv_bfloat16 g_y_lo[SZ];
// segment scan scratch: consts (phase A) and prefixes (phase B)
__device__ float g_sca[NSEGST], g_scb[NSEGST], g_sco[NSEGST];
__device__ float g_pa[NSEGST],  g_pb[NSEGST],  g_po[NSEGST];

// ------------------------------ PTX helpers --------------------------------
__device__ __forceinline__ uint32_t smem_u32(const void* p) {
    uint32_t a;
    asm("{ .reg .u64 t; cvta.to.shared.u64 t, %1; cvt.u32.u64 %0, t; }"
        : "=r"(a) : "l"(p));
    return a;
}
__device__ __forceinline__ void cp16(uint32_t dst, const void* src) {
    asm volatile("cp.async.cg.shared.global [%0], [%1], 16;" :: "r"(dst), "l"(src));
}
#define CP_COMMIT() asm volatile("cp.async.commit_group;" ::: "memory")
#define CP_WAIT(n)  asm volatile("cp.async.wait_group %0;" :: "n"(n) : "memory")

__device__ __forceinline__ void ldsm4(uint32_t* r, uint32_t a) {
    asm volatile("ldmatrix.sync.aligned.m8n8.x4.shared.b16 {%0,%1,%2,%3}, [%4];"
        : "=r"(r[0]), "=r"(r[1]), "=r"(r[2]), "=r"(r[3]) : "r"(a));
}
__device__ __forceinline__ void mma16816(float* c, const uint32_t* a, const uint32_t* b) {
    asm volatile("mma.sync.aligned.m16n8k16.row.col.f32.bf16.bf16.f32 "
        "{%0,%1,%2,%3}, {%4,%5,%6,%7}, {%8,%9}, {%0,%1,%2,%3};"
        : "+f"(c[0]), "+f"(c[1]), "+f"(c[2]), "+f"(c[3])
        : "r"(a[0]), "r"(a[1]), "r"(a[2]), "r"(a[3]), "r"(b[0]), "r"(b[1]));
}

__device__ __forceinline__ void split2(float a, float b, uint32_t& h2, uint32_t& l2) {
    asm("cvt.rn.bf16x2.f32 %0, %1, %2;" : "=r"(h2) : "f"(b), "f"(a));
    float ha = __uint_as_float(h2 << 16);
    float hb = __uint_as_float(h2 & 0xFFFF0000u);
    asm("cvt.rn.bf16x2.f32 %0, %1, %2;" : "=r"(l2) : "f"(b - hb), "f"(a - ha));
}

// ------------------------------ GEMM config (R8) ---------------------------
#define CTA_M 256
#define CTA_N 128
#define KCHUNK 32
#define NCHUNK (CC / KCHUNK)       // 32
#define LDS_ROW 40                  // bf16/row: 32 data + 8 pad
#define ROWB (LDS_ROW * 2)          // 80 bytes; conflict-free ldmatrix stride
#define SM_AH 0
#define SM_AL 20480                 // 256*80
#define SM_WH 40960
#define SM_WL 51200                 // +128*80
#define STAGE 61440
#define SMEM_BYTES (2 * STAGE)      // 122880

__device__ __forceinline__ void gemm_mma_body(
    const __nv_bfloat16* __restrict__ Ahi, const __nv_bfloat16* __restrict__ Alo,
    const __nv_bfloat16* __restrict__ Whi, const __nv_bfloat16* __restrict__ Wlo,
    float* __restrict__ D)
{
    extern __shared__ char smem[];
    const uint32_t sb = smem_u32(smem);
    const int tid = threadIdx.x;
    const int wid = tid >> 5;
    const int lane = tid & 31;
    const int wm = wid >> 1;
    const int wn = wid & 1;
    const int gm = blockIdx.y * CTA_M;
    const int gn = blockIdx.x * CTA_N;

    float acc[4][8][4];
#pragma unroll
    for (int i = 0; i < 4; i++)
#pragma unroll
        for (int j = 0; j < 8; j++)
#pragma unroll
            for (int q = 0; q < 4; q++) acc[i][j][q] = 0.f;

    const int a_row = wm * 64 + (lane & 7) + ((lane >> 3) & 1) * 8;
    const int a_kof = (lane >> 4) * 8;
    const int b_row = wn * 64 + lane;

    const __nv_bfloat16* gA[2] = { Ahi + (size_t)gm * CC, Alo + (size_t)gm * CC };
    const __nv_bfloat16* gW[2] = { Whi + (size_t)gn * CC, Wlo + (size_t)gn * CC };

#define LOAD_CHUNK(ck, stg) do {                                              \
    uint32_t s0 = sb + (stg) * STAGE;                                         \
    int kc = (ck) * KCHUNK;                                                   \
    _Pragma("unroll")                                                         \
    for (int i = 0; i < 12; i++) {                                            \
        int idx = tid + i * 256;                                              \
        if (i < 8) {                                                          \
            int ty = idx >> 10, rem = idx & 1023;                             \
            int row = rem >> 2, c = rem & 3;                                  \
            cp16(s0 + ty * 20480 + row * ROWB + c * 16,                       \
                 gA[ty] + (size_t)row * CC + kc + c * 8);                     \
        } else {                                                              \
            int w = idx - 2048;                                               \
            int ty = w >> 9, rem = w & 511;                                   \
            int row = rem >> 2, c = rem & 3;                                  \
            cp16(s0 + 40960 + ty * 10240 + row * ROWB + c * 16,               \
                 gW[ty] + (size_t)row * CC + kc + c * 8);                     \
        }                                                                     \
    }                                                                         \
    CP_COMMIT();                                                              \
} while (0)

    LOAD_CHUNK(0, 0);

    for (int ck = 0; ck < NCHUNK; ck++) {
        const int stg = ck & 1;
        if (ck + 1 < NCHUNK) { LOAD_CHUNK(ck + 1, stg ^ 1); CP_WAIT(1); }
        else                 { CP_WAIT(0); }
        __syncthreads();

        const uint32_t s0 = sb + stg * STAGE;
#pragma unroll
        for (int k0 = 0; k0 < KCHUNK; k0 += 16) {
            uint32_t ah[4][4], al[4][4];
#pragma unroll
            for (int mi = 0; mi < 4; mi++) {
                uint32_t addr = s0 + SM_AH + (uint32_t)((a_row + mi * 16) * ROWB + (k0 + a_kof) * 2);
                ldsm4(ah[mi], addr);
                ldsm4(al[mi], addr + (SM_AL - SM_AH));
            }
#pragma unroll
            for (int g = 0; g < 2; g++) {
                uint32_t t0[4], t1[4], u0[4], u1[4];
                uint32_t base = s0 + SM_WH + (uint32_t)((b_row + g * 32) * ROWB + k0 * 2);
                ldsm4(t0, base);
                ldsm4(t1, base + 16);
                ldsm4(u0, base + (SM_WL - SM_WH));
                ldsm4(u1, base + (SM_WL - SM_WH) + 16);
#pragma unroll
                for (int s = 0; s < 4; s++) {
                    uint32_t bh[2] = { t0[s], t1[s] };
                    uint32_t bl[2] = { u0[s], u1[s] };
#pragma unroll
                    for (int mi = 0; mi < 4; mi++) {
                        float* a = acc[mi][g * 4 + s];
                        mma16816(a, ah[mi], bh);
                        mma16816(a, ah[mi], bl);
                        mma16816(a, al[mi], bh);
                    }
                }
            }
        }
        __syncthreads();
    }
#undef LOAD_CHUNK

    const int trow = lane >> 2;
    const int tcol = (lane & 3) * 2;
#pragma unroll
    for (int mi = 0; mi < 4; mi++) {
#pragma unroll
        for (int ni = 0; ni < 8; ni++) {
            float* dp = D + (size_t)(gm + wm * 64 + mi * 16 + trow) * CC
                          + gn + wn * 64 + ni * 8 + tcol;
            float2 v0 = { acc[mi][ni][0], acc[mi][ni][1] };
            float2 v1 = { acc[mi][ni][2], acc[mi][ni][3] };
            *(float2*)dp = v0;
            *(float2*)(dp + 8 * CC) = v1;
        }
    }
}

__global__ __launch_bounds__(256, 1)
void gemm3_mma() {
    const int z = blockIdx.z;
    gemm_mma_body(g_a_hi + (size_t)z * SZ, g_a_lo + (size_t)z * SZ,
                  g_w_hi + (size_t)z * WSZ, g_w_lo + (size_t)z * WSZ,
                  g_kvr + (size_t)z * SZ);
}

__global__ __launch_bounds__(256, 1)
void gemm_out_mma(float* __restrict__ out) {
    gemm_mma_body(g_y_hi, g_y_lo, g_w_hi + 3 * WSZ, g_w_lo + 3 * WSZ, out);
}

// ------------------------------- mix kernel ---------------------------------
__global__ void mix_kernel(const float* __restrict__ x,
                           const float* __restrict__ tmk,
                           const float* __restrict__ tmv,
                           const float* __restrict__ tmr) {
    const int n4 = SZ / 4;
    int i = blockIdx.x * blockDim.x + threadIdx.x;
    if (i >= n4) return;
    const int cpt = CC / 4;
    int c4 = i & (cpt - 1);
    int t  = (i / cpt) & (TT - 1);

    const float4* x4 = (const float4*)x;
    float4 xc = x4[i];
    float4 xp = make_float4(0.f, 0.f, 0.f, 0.f);
    if (t != 0) xp = x4[i - cpt];

    const float4 ms[3] = { ((const float4*)tmk)[c4],
                           ((const float4*)tmv)[c4],
                           ((const float4*)tmr)[c4] };
#pragma unroll
    for (int z = 0; z < 3; z++) {
        float4 m = ms[z];
        float a = xp.x + m.x * (xc.x - xp.x);
        float b = xp.y + m.y * (xc.y - xp.y);
        float c = xp.z + m.z * (xc.z - xp.z);
        float d = xp.w + m.w * (xc.w - xp.w);
        uint2 h, l;
        split2(a, b, h.x, l.x);
        split2(c, d, h.y, l.y);
        ((uint2*)g_a_hi)[(size_t)z * (SZ / 4) + i] = h;
        ((uint2*)g_a_lo)[(size_t)z * (SZ / 4) + i] = l;
    }
}

// --------------------------- weight split kernel ----------------------------
__global__ void wsplit_kernel(const float* __restrict__ Wk, const float* __restrict__ Wv,
                              const float* __restrict__ Wr, const float* __restrict__ Wo) {
    int i = blockIdx.x * blockDim.x + threadIdx.x;
    const int per = WSZ / 4;
    if (i >= 4 * per) return;
    int z = i >> 18;
    int loc = i & (per - 1);
    const float* W = (z == 0) ? Wk : (z == 1) ? Wv : (z == 2) ? Wr : Wo;
    float4 v = ((const float4*)W)[loc];
    uint2 h, l;
    split2(v.x, v.y, h.x, l.x);
    split2(v.z, v.w, h.y, l.y);
    ((uint2*)g_w_hi)[(size_t)z * per + loc] = h;
    ((uint2*)g_w_lo)[(size_t)z * per + loc] = l;
}

// ----------------------- WKV: 3-phase parallel scan -------------------------
// Stabilized state (p, q, o) represents true (p*e^o, q*e^o). Over a segment of
// L steps the true state transforms affinely with multiplier e^{L*w}, so
// segments compose: A computes per-segment sums; B combines prefixes; C
// replays each segment from its prefix emitting gated outputs.

// Phase A: per (b,seg,c), segment-local sums from zero state.
__global__ void wkv_segA(const float* __restrict__ time_decay) {
    int gid = blockIdx.x * blockDim.x + threadIdx.x;
    if (gid >= NSEGST) return;
    int c = gid & (CC - 1);
    int s = (gid >> 10) & (SEG - 1);
    int b = gid >> 13;

    float w = -__expf(time_decay[c]);
    const float* kk = g_kvr;
    const float* vv = g_kvr + SZ;
    size_t off = ((size_t)(b * TT + s * SEGLEN)) * CC + c;

    float ca = 0.f, cb = 0.f, oo = -1e38f;
#pragma unroll 4
    for (int t = 0; t < SEGLEN; t++, off += CC) {
        float kt = kk[off];
        float vt = vv[off];
        float wo = w + oo;
        float no = fmaxf(wo, kt);
        float A2 = __expf(wo - no);
        float B2 = __expf(kt - no);
        ca = A2 * ca + B2 * vt;
        cb = A2 * cb + B2;
        oo = no;
    }
    g_sca[gid] = ca;
    g_scb[gid] = cb;
    g_sco[gid] = oo;
}

// Phase B: per (b,c), combine segment transforms; store incoming prefixes.
__global__ void wkv_segB(const float* __restrict__ time_decay) {
    int gid = blockIdx.x * blockDim.x + threadIdx.x;
    if (gid >= BB * CC) return;
    int c = gid & (CC - 1);
    int b = gid >> 10;

    float w = -__expf(time_decay[c]);
    float dec = (float)SEGLEN * w;

    float a = 0.f, q = 0.f, oo = -1e38f;
#pragma unroll
    for (int s = 0; s < SEG; s++) {
        int idx = (b * SEG + s) * CC + c;
        g_pa[idx] = a;
        g_pb[idx] = q;
        g_po[idx] = oo;
        float od = oo + dec;
        float co = g_sco[idx];
        float no = fmaxf(od, co);
        float e1 = __expf(od - no);
        float e2 = __expf(co - no);
        a  = e1 * a + e2 * g_sca[idx];
        q  = e1 * q + e2 * g_scb[idx];
        oo = no;
    }
}

// Phase C: per (b,seg,c), replay from prefix, emit sigmoid(r)*y (bf16 split).
__global__ void wkv_segC(const float* __restrict__ time_decay,
                         const float* __restrict__ time_first) {
    int gid = blockIdx.x * blockDim.x + threadIdx.x;
    if (gid >= NSEGST) return;
    int c = gid & (CC - 1);
    int s = (gid >> 10) & (SEG - 1);
    int b = gid >> 13;

    float w = -__expf(time_decay[c]);
    float u = time_first[c];

    const float* kk = g_kvr;
    const float* vv = g_kvr + SZ;
    const float* rr = g_kvr + 2 * (size_t)SZ;

    float p = g_pa[gid];
    float q = g_pb[gid];
    float o = g_po[gid];
    size_t off = ((size_t)(b * TT + s * SEGLEN)) * CC + c;

#pragma unroll 4
    for (int t = 0; t < SEGLEN; t++, off += CC) {
        float kt = kk[off];
        float vt = vv[off];
        float rt = rr[off];

        float uk = u + kt;
        float no = fmaxf(o, uk);
        float eA = __expf(o - no);
        float eB = __expf(uk - no);
        float y  = __fdividef(eA * p + eB * vt, eA * q + eB);

        float sr = __fdividef(1.f, 1.f + __expf(-rt));
        float f = sr * y;
        __nv_bfloat16 h = __float2bfloat16(f);
        g_y_hi[off] = h;
        g_y_lo[off] = __float2bfloat16(f - __bfloat162float(h));

        float wo  = w + o;
        float no2 = fmaxf(wo, kt);
        float A2  = __expf(wo - no2);
        float B2  = __expf(kt - no2);
        p = A2 * p + B2 * vt;
        q = A2 * q + B2;
        o = no2;
    }
}

// ---------------------------------------------------------------------------
extern "C" void kernel_launch(void* const* d_in, const int* in_sizes, int n_in,
                              void* d_out, int out_size) {
    const float* x   = (const float*)d_in[0];
    const float* td  = (const float*)d_in[1];
    const float* tf  = (const float*)d_in[2];
    const float* tmk = (const float*)d_in[3];
    const float* tmv = (const float*)d_in[4];
    const float* tmr = (const float*)d_in[5];
    const float* Wk  = (const float*)d_in[6];
    const float* Wv  = (const float*)d_in[7];
    const float* Wr  = (const float*)d_in[8];
    const float* Wo  = (const float*)d_in[9];
    float* out = (float*)d_out;

    static bool attr_set = false;
    if (!attr_set) {
        cudaFuncSetAttribute(gemm3_mma, cudaFuncAttributeMaxDynamicSharedMemorySize, SMEM_BYTES);
        cudaFuncSetAttribute(gemm_out_mma, cudaFuncAttributeMaxDynamicSharedMemorySize, SMEM_BYTES);
        attr_set = true;
    }

    const int n4 = SZ / 4;
    mix_kernel<<<(n4 + 255) / 256, 256>>>(x, tmk, tmv, tmr);
    wsplit_kernel<<<(WSZ + 255) / 256, 256>>>(Wk, Wv, Wr, Wo);

    dim3 g3(CC / CTA_N, MROWS / CTA_M, 3);
    gemm3_mma<<<g3, 256, SMEM_BYTES>>>();

    wkv_segA<<<(NSEGST + 255) / 256, 256>>>(td);
    wkv_segB<<<(BB * CC + 255) / 256, 256>>>(td);
    wkv_segC<<<(NSEGST + 255) / 256, 256>>>(td, tf);

    dim3 go(CC / CTA_N, MROWS / CTA_M, 1);
    gemm_out_mma<<<go, 256, SMEM_BYTES>>>(out);
}

// round 13
// speedup vs baseline: 2.0018x; 1.2539x over previous
#include <cuda_runtime.h>
#include <cuda_bf16.h>
#include <cstdint>

// RWKV TimeMix on GB300 (compute_103-safe tensor path):
//   mix(bf16 split, K-blocked+swizzled layout) -> 3x HMMA GEMM (bulk-copy
//   pipelined) -> WKV 3-phase parallel scan -> HMMA output GEMM.
// GEMM: D[m,d] = sum_c A[m,c]*W[d,c]; fp32 accuracy via bf16 3-term split:
//   D = Ah*Wh + Ah*Wl + Al*Wh     (lo*lo dropped, ~2^-18 relative)
// Operands for GEMMs live in a K-chunk-blocked gmem layout: chunk ck holds a
// contiguous [rows x 64] tile with 128B rows and SW128 swizzle PRE-APPLIED,
// so a single 1D cp.async.bulk per operand per chunk lands ldmatrix-ready.

#define BB 32
#define TT 256
#define CC 1024
#define MROWS (BB * TT)                 // 8192
#define SZ (BB * TT * CC)               // 8,388,608
#define WSZ (CC * CC)                   // 1,048,576
#define SEG 8
#define SEGLEN (TT / SEG)               // 32
#define NSEGST (BB * SEG * CC)          // 262144

// ------------------------- device scratch (no allocs) -----------------------
__device__ __nv_bfloat16 g_a_hi[3 * SZ];   // blocked+swizzled
__device__ __nv_bfloat16 g_a_lo[3 * SZ];
__device__ __nv_bfloat16 g_w_hi[4 * WSZ];  // blocked+swizzled
__device__ __nv_bfloat16 g_w_lo[4 * WSZ];
__device__ float         g_kvr[3 * SZ];    // linear [m][c]
__device__ __nv_bfloat16 g_y_hi[SZ];       // blocked+swizzled
__device__ __nv_bfloat16 g_y_lo[SZ];
__device__ float g_sca[NSEGST], g_scb[NSEGST], g_sco[NSEGST];
__device__ float g_pa[NSEGST],  g_pb[NSEGST],  g_po[NSEGST];

// ------------------------------ PTX helpers --------------------------------
__device__ __forceinline__ uint32_t smem_u32(const void* p) {
    uint32_t a;
    asm("{ .reg .u64 t; cvta.to.shared.u64 t, %1; cvt.u32.u64 %0, t; }"
        : "=r"(a) : "l"(p));
    return a;
}
__device__ __forceinline__ uint32_t sw128(uint32_t o) {
    return o ^ ((o >> 3) & 0x70);
}
__device__ __forceinline__ void bulk_g2s(uint32_t dst, const void* src,
                                         uint32_t bytes, uint32_t mbar) {
    asm volatile(
        "cp.async.bulk.shared::cluster.global.mbarrier::complete_tx::bytes "
        "[%0], [%1], %2, [%3];"
        :: "r"(dst), "l"(src), "r"(bytes), "r"(mbar) : "memory");
}
#define MBAR_INIT(mb, n) \
    asm volatile("mbarrier.init.shared.b64 [%0], %1;" :: "r"(mb), "r"(n) : "memory")
#define MBAR_EXPECT_TX(mb, bytes) \
    asm volatile("mbarrier.arrive.expect_tx.shared.b64 _, [%0], %1;" \
                 :: "r"(mb), "r"(bytes) : "memory")
#define MBAR_WAIT(mb, par) do {                                                   \
    uint32_t _m = (mb), _p = (par), _d;                                           \
    asm volatile("{ .reg .pred p;"                                                \
        " mbarrier.try_wait.parity.acquire.cta.shared::cta.b64 p, [%1], %2;"      \
        " selp.b32 %0,1,0,p; }" : "=r"(_d) : "r"(_m), "r"(_p) : "memory");        \
    if (!_d) {                                                                    \
        asm volatile("{ .reg .pred P;"                                            \
            "WL_%=: mbarrier.try_wait.parity.acquire.cta.shared::cta.b64 P, [%0], %1, 0x989680;" \
            " @P bra.uni WD_%=;  bra.uni WL_%=;  WD_%=: }"                        \
            :: "r"(_m), "r"(_p) : "memory");                                      \
    }                                                                             \
} while (0)

__device__ __forceinline__ void ldsm4(uint32_t* r, uint32_t a) {
    asm volatile("ldmatrix.sync.aligned.m8n8.x4.shared.b16 {%0,%1,%2,%3}, [%4];"
        : "=r"(r[0]), "=r"(r[1]), "=r"(r[2]), "=r"(r[3]) : "r"(a));
}
__device__ __forceinline__ void mma16816(float* c, const uint32_t* a, const uint32_t* b) {
    asm volatile("mma.sync.aligned.m16n8k16.row.col.f32.bf16.bf16.f32 "
        "{%0,%1,%2,%3}, {%4,%5,%6,%7}, {%8,%9}, {%0,%1,%2,%3};"
        : "+f"(c[0]), "+f"(c[1]), "+f"(c[2]), "+f"(c[3])
        : "r"(a[0]), "r"(a[1]), "r"(a[2]), "r"(a[3]), "r"(b[0]), "r"(b[1]));
}
__device__ __forceinline__ void split2(float a, float b, uint32_t& h2, uint32_t& l2) {
    asm("cvt.rn.bf16x2.f32 %0, %1, %2;" : "=r"(h2) : "f"(b), "f"(a));
    float ha = __uint_as_float(h2 << 16);
    float hb = __uint_as_float(h2 & 0xFFFF0000u);
    asm("cvt.rn.bf16x2.f32 %0, %1, %2;" : "=r"(l2) : "f"(b - hb), "f"(a - ha));
}

// Blocked-layout byte offsets (KCHUNK=64, 128B rows, SW128 baked in).
__device__ __forceinline__ size_t ablk(int m, int c) {     // activations / y
    uint32_t o = (uint32_t)m * 128 + (c & 63) * 2;
    return (size_t)(c >> 6) * (MROWS * 128) + sw128(o);
}
__device__ __forceinline__ size_t wblk(int n, int c) {     // weights
    uint32_t o = (uint32_t)n * 128 + (c & 63) * 2;
    return (size_t)(c >> 6) * (CC * 128) + sw128(o);
}

// ------------------------------ GEMM config --------------------------------
#define CTA_M 256
#define CTA_N 128
#define KCHUNK 64
#define NCHUNK (CC / KCHUNK)       // 16
#define SM_AH 0
#define SM_AL 32768
#define SM_WH 65536
#define SM_WL 81920
#define STAGE 98304
#define CHUNK_BYTES 98304
#define SMEM_BYTES (2 * STAGE + 64)   // 196672

__device__ __forceinline__ void gemm_mma_body(
    const char* __restrict__ Ahb, const char* __restrict__ Alb,
    const char* __restrict__ Whb, const char* __restrict__ Wlb,
    float* __restrict__ D)
{
    extern __shared__ char smem[];
    const uint32_t sb = smem_u32(smem);
    const uint32_t mbb = sb + 2 * STAGE;       // two 8B mbarriers
    const int tid = threadIdx.x;
    const int wid = tid >> 5;
    const int lane = tid & 31;
    const int wm = wid >> 1;
    const int wn = wid & 1;
    const int gm = blockIdx.y * CTA_M;
    const int gn = blockIdx.x * CTA_N;

    if (tid == 0) { MBAR_INIT(mbb, 1); MBAR_INIT(mbb + 8, 1); }
    __syncthreads();

#define ISSUE(ck, s) do {                                                     \
    uint32_t _mb = mbb + 8 * (s);                                             \
    uint32_t _d  = sb + (s) * STAGE;                                          \
    MBAR_EXPECT_TX(_mb, CHUNK_BYTES);                                         \
    bulk_g2s(_d + SM_AH, Ahb + (size_t)(ck) * (MROWS * 128) + gm * 128, 32768, _mb); \
    bulk_g2s(_d + SM_AL, Alb + (size_t)(ck) * (MROWS * 128) + gm * 128, 32768, _mb); \
    bulk_g2s(_d + SM_WH, Whb + (size_t)(ck) * (CC * 128) + gn * 128, 16384, _mb);    \
    bulk_g2s(_d + SM_WL, Wlb + (size_t)(ck) * (CC * 128) + gn * 128, 16384, _mb);    \
} while (0)

    if (tid == 0) { ISSUE(0, 0); ISSUE(1, 1); }

    float acc[4][8][4];
#pragma unroll
    for (int i = 0; i < 4; i++)
#pragma unroll
        for (int j = 0; j < 8; j++)
#pragma unroll
            for (int q = 0; q < 4; q++) acc[i][j][q] = 0.f;

    const int a_row = wm * 64 + (lane & 7) + ((lane >> 3) & 1) * 8;  // + mi*16
    const int a_kof = (lane >> 4) * 8;                               // + k0
    const int b_row = wn * 64 + lane;                                // + g*32

    for (int ck = 0; ck < NCHUNK; ck++) {
        const int s = ck & 1;
        MBAR_WAIT(mbb + 8 * s, (ck >> 1) & 1);
        const uint32_t s0 = sb + s * STAGE;

#pragma unroll
        for (int k0 = 0; k0 < KCHUNK; k0 += 16) {
            uint32_t ah[4][4], al[4][4];
#pragma unroll
            for (int mi = 0; mi < 4; mi++) {
                uint32_t o = (uint32_t)(a_row + mi * 16) * 128 + (k0 + a_kof) * 2;
                ah[mi][0] = 0; // placeholder to keep arrays in regs
                ldsm4(ah[mi], s0 + SM_AH + sw128(o));
                ldsm4(al[mi], s0 + SM_AL + sw128(o));
            }
#pragma unroll
            for (int g = 0; g < 2; g++) {
                uint32_t t0[4], t1[4], u0[4], u1[4];
                uint32_t o0 = (uint32_t)(b_row + g * 32) * 128 + k0 * 2;
                uint32_t o1 = o0 + 16;           // k-half 1 (8 cols)
                ldsm4(t0, s0 + SM_WH + sw128(o0));
                ldsm4(t1, s0 + SM_WH + sw128(o1));
                ldsm4(u0, s0 + SM_WL + sw128(o0));
                ldsm4(u1, s0 + SM_WL + sw128(o1));
#pragma unroll
                for (int ss = 0; ss < 4; ss++) {
                    uint32_t bh[2] = { t0[ss], t1[ss] };
                    uint32_t bl[2] = { u0[ss], u1[ss] };
#pragma unroll
                    for (int mi = 0; mi < 4; mi++) {
                        float* a = acc[mi][g * 4 + ss];
                        mma16816(a, ah[mi], bh);
                        mma16816(a, ah[mi], bl);
                        mma16816(a, al[mi], bh);
                    }
                }
            }
        }
        __syncthreads();
        if (ck + 2 < NCHUNK && tid == 0) ISSUE(ck + 2, s);
    }
#undef ISSUE

    const int trow = lane >> 2;
    const int tcol = (lane & 3) * 2;
#pragma unroll
    for (int mi = 0; mi < 4; mi++) {
#pragma unroll
        for (int ni = 0; ni < 8; ni++) {
            float* dp = D + (size_t)(gm + wm * 64 + mi * 16 + trow) * CC
                          + gn + wn * 64 + ni * 8 + tcol;
            float2 v0 = { acc[mi][ni][0], acc[mi][ni][1] };
            float2 v1 = { acc[mi][ni][2], acc[mi][ni][3] };
            *(float2*)dp = v0;
            *(float2*)(dp + 8 * CC) = v1;
        }
    }
}

__global__ __launch_bounds__(256, 1)
void gemm3_mma() {
    const int z = blockIdx.z;
    gemm_mma_body((const char*)g_a_hi + (size_t)z * SZ * 2,
                  (const char*)g_a_lo + (size_t)z * SZ * 2,
                  (const char*)g_w_hi + (size_t)z * WSZ * 2,
                  (const char*)g_w_lo + (size_t)z * WSZ * 2,
                  g_kvr + (size_t)z * SZ);
}

__global__ __launch_bounds__(256, 1)
void gemm_out_mma(float* __restrict__ out) {
    gemm_mma_body((const char*)g_y_hi, (const char*)g_y_lo,
                  (const char*)g_w_hi + (size_t)3 * WSZ * 2,
                  (const char*)g_w_lo + (size_t)3 * WSZ * 2, out);
}

// ------------------------------- mix kernel ---------------------------------
// Writes xk/xv/xr directly into the blocked+swizzled layout.
__global__ void mix_kernel(const float* __restrict__ x,
                           const float* __restrict__ tmk,
                           const float* __restrict__ tmv,
                           const float* __restrict__ tmr) {
    const int n4 = SZ / 4;
    int i = blockIdx.x * blockDim.x + threadIdx.x;
    if (i >= n4) return;
    const int cpt = CC / 4;                 // 256 float4 per row
    int c4 = i & (cpt - 1);
    int m  = i >> 8;                        // global row (b*TT + t)
    int t  = m & (TT - 1);
    int c  = c4 * 4;

    const float4* x4 = (const float4*)x;
    float4 xc = x4[i];
    float4 xp = make_float4(0.f, 0.f, 0.f, 0.f);
    if (t != 0) xp = x4[i - cpt];

    const float4 ms[3] = { ((const float4*)tmk)[c4],
                           ((const float4*)tmv)[c4],
                           ((const float4*)tmr)[c4] };
    const size_t off = ablk(m, c);
#pragma unroll
    for (int z = 0; z < 3; z++) {
        float4 mm = ms[z];
        float a = xp.x + mm.x * (xc.x - xp.x);
        float b = xp.y + mm.y * (xc.y - xp.y);
        float c2 = xp.z + mm.z * (xc.z - xp.z);
        float d = xp.w + mm.w * (xc.w - xp.w);
        uint2 h, l;
        split2(a, b, h.x, l.x);
        split2(c2, d, h.y, l.y);
        *(uint2*)((char*)g_a_hi + (size_t)z * SZ * 2 + off) = h;
        *(uint2*)((char*)g_a_lo + (size_t)z * SZ * 2 + off) = l;
    }
}

// --------------------------- weight split kernel ----------------------------
__global__ void wsplit_kernel(const float* __restrict__ Wk, const float* __restrict__ Wv,
                              const float* __restrict__ Wr, const float* __restrict__ Wo) {
    int i = blockIdx.x * blockDim.x + threadIdx.x;
    const int per = WSZ / 4;
    if (i >= 4 * per) return;
    int z = i >> 18;
    int loc = i & (per - 1);
    int n = loc >> 8;
    int c = (loc & 255) * 4;
    const float* W = (z == 0) ? Wk : (z == 1) ? Wv : (z == 2) ? Wr : Wo;
    float4 v = ((const float4*)W)[loc];
    uint2 h, l;
    split2(v.x, v.y, h.x, l.x);
    split2(v.z, v.w, h.y, l.y);
    const size_t off = wblk(n, c);
    *(uint2*)((char*)g_w_hi + (size_t)z * WSZ * 2 + off) = h;
    *(uint2*)((char*)g_w_lo + (size_t)z * WSZ * 2 + off) = l;
}

// ----------------------- WKV: 3-phase parallel scan -------------------------
__global__ void wkv_segA(const float* __restrict__ time_decay) {
    int gid = blockIdx.x * blockDim.x + threadIdx.x;
    if (gid >= NSEGST) return;
    int c = gid & (CC - 1);
    int s = (gid >> 10) & (SEG - 1);
    int b = gid >> 13;

    float w = -__expf(time_decay[c]);
    const float* kk = g_kvr;
    const float* vv = g_kvr + SZ;
    size_t off = ((size_t)(b * TT + s * SEGLEN)) * CC + c;

    float ca = 0.f, cb = 0.f, oo = -1e38f;
#pragma unroll 4
    for (int t = 0; t < SEGLEN; t++, off += CC) {
        float kt = kk[off];
        float vt = vv[off];
        float wo = w + oo;
        float no = fmaxf(wo, kt);
        float A2 = __expf(wo - no);
        float B2 = __expf(kt - no);
        ca = A2 * ca + B2 * vt;
        cb = A2 * cb + B2;
        oo = no;
    }
    g_sca[gid] = ca;
    g_scb[gid] = cb;
    g_sco[gid] = oo;
}

__global__ void wkv_segB(const float* __restrict__ time_decay) {
    int gid = blockIdx.x * blockDim.x + threadIdx.x;
    if (gid >= BB * CC) return;
    int c = gid & (CC - 1);
    int b = gid >> 10;

    float w = -__expf(time_decay[c]);
    float dec = (float)SEGLEN * w;

    float a = 0.f, q = 0.f, oo = -1e38f;
#pragma unroll
    for (int s = 0; s < SEG; s++) {
        int idx = (b * SEG + s) * CC + c;
        g_pa[idx] = a;
        g_pb[idx] = q;
        g_po[idx] = oo;
        float od = oo + dec;
        float co = g_sco[idx];
        float no = fmaxf(od, co);
        float e1 = __expf(od - no);
        float e2 = __expf(co - no);
        a  = e1 * a + e2 * g_sca[idx];
        q  = e1 * q + e2 * g_scb[idx];
        oo = no;
    }
}

__global__ void wkv_segC(const float* __restrict__ time_decay,
                         const float* __restrict__ time_first) {
    int gid = blockIdx.x * blockDim.x + threadIdx.x;
    if (gid >= NSEGST) return;
    int c = gid & (CC - 1);
    int s = (gid >> 10) & (SEG - 1);
    int b = gid >> 13;

    float w = -__expf(time_decay[c]);
    float u = time_first[c];

    const float* kk = g_kvr;
    const float* vv = g_kvr + SZ;
    const float* rr = g_kvr + 2 * (size_t)SZ;

    float p = g_pa[gid];
    float q = g_pb[gid];
    float o = g_po[gid];
    int m0 = b * TT + s * SEGLEN;
    size_t off = (size_t)m0 * CC + c;

#pragma unroll 4
    for (int t = 0; t < SEGLEN; t++, off += CC) {
        float kt = kk[off];
        float vt = vv[off];
        float rt = rr[off];

        float uk = u + kt;
        float no = fmaxf(o, uk);
        float eA = __expf(o - no);
        float eB = __expf(uk - no);
        float y  = __fdividef(eA * p + eB * vt, eA * q + eB);

        float sr = __fdividef(1.f, 1.f + __expf(-rt));
        float f = sr * y;
        __nv_bfloat16 h = __float2bfloat16(f);
        size_t bo = ablk(m0 + t, c);
        *(__nv_bfloat16*)((char*)g_y_hi + bo) = h;
        *(__nv_bfloat16*)((char*)g_y_lo + bo) =
            __float2bfloat16(f - __bfloat162float(h));

        float wo  = w + o;
        float no2 = fmaxf(wo, kt);
        float A2  = __expf(wo - no2);
        float B2  = __expf(kt - no2);
        p = A2 * p + B2 * vt;
        q = A2 * q + B2;
        o = no2;
    }
}

// ---------------------------------------------------------------------------
extern "C" void kernel_launch(void* const* d_in, const int* in_sizes, int n_in,
                              void* d_out, int out_size) {
    const float* x   = (const float*)d_in[0];
    const float* td  = (const float*)d_in[1];
    const float* tf  = (const float*)d_in[2];
    const float* tmk = (const float*)d_in[3];
    const float* tmv = (const float*)d_in[4];
    const float* tmr = (const float*)d_in[5];
    const float* Wk  = (const float*)d_in[6];
    const float* Wv  = (const float*)d_in[7];
    const float* Wr  = (const float*)d_in[8];
    const float* Wo  = (const float*)d_in[9];
    float* out = (float*)d_out;

    static bool attr_set = false;
    if (!attr_set) {
        cudaFuncSetAttribute(gemm3_mma, cudaFuncAttributeMaxDynamicSharedMemorySize, SMEM_BYTES);
        cudaFuncSetAttribute(gemm_out_mma, cudaFuncAttributeMaxDynamicSharedMemorySize, SMEM_BYTES);
        attr_set = true;
    }

    const int n4 = SZ / 4;
    mix_kernel<<<(n4 + 255) / 256, 256>>>(x, tmk, tmv, tmr);
    wsplit_kernel<<<(WSZ + 255) / 256, 256>>>(Wk, Wv, Wr, Wo);

    dim3 g3(CC / CTA_N, MROWS / CTA_M, 3);
    gemm3_mma<<<g3, 256, SMEM_BYTES>>>();

    wkv_segA<<<(NSEGST + 255) / 256, 256>>>(td);
    wkv_segB<<<(BB * CC + 255) / 256, 256>>>(td);
    wkv_segC<<<(NSEGST + 255) / 256, 256>>>(td, tf);

    dim3 go(CC / CTA_N, MROWS / CTA_M, 1);
    gemm_out_mma<<<go, 256, SMEM_BYTES>>>(out);
}